// round 4
// baseline (speedup 1.0000x reference)
#include <cuda_runtime.h>
#include <cstdint>

#define Bn 16
#define Cc 128
#define Hh 64
#define Ww 64

// ---- scratch: tf32-pre-rounded weights [b][tap][co][ci] and inputs [b][ci][h][w] ----
__device__ uint32_t g_wt[(size_t)Bn * 9 * Cc * Cc];
__device__ uint32_t g_xt[(size_t)Bn * Cc * Hh * Ww];

__device__ __forceinline__ uint32_t f2tf32(float x) {
    uint32_t r;
    asm("cvt.rna.tf32.f32 %0, %1;" : "=r"(r) : "f"(x));
    return r;
}

__global__ void prep_w(const float* __restrict__ w) {
    int idx = blockIdx.x * blockDim.x + threadIdx.x;  // 2359296 total
    int ci   = idx & 127;
    int co   = (idx >> 7) & 127;
    int rest = idx >> 14;      // b*9 + t
    int t    = rest % 9;
    int b    = rest / 9;
    g_wt[idx] = f2tf32(w[((size_t)(b * Cc + co) * Cc + ci) * 9 + t]);
}

__global__ void prep_x(const float* __restrict__ x) {
    int idx = blockIdx.x * blockDim.x + threadIdx.x;  // 2097152 float4s
    float4 v = ((const float4*)x)[idx];
    uint4 u;
    u.x = f2tf32(v.x); u.y = f2tf32(v.y);
    u.z = f2tf32(v.z); u.w = f2tf32(v.w);
    ((uint4*)g_xt)[idx] = u;
}

// ---- main kernel ----
// CTA tile: M=128 (all co) x N=128 (2 rows x 64 w), K chunked by 8 ci. 256 thr, 2 CTA/SM.
// X tile [8 ci][4 rows][76], ci-stride 312 (==24 mod 32, conflict-free), w=0 at slot 4.
// W tile [9 tap][128 co][8], slot = k ^ (co&4) XOR swizzle (conflict-free A frags, 16B cp.async ok).
#define XBUF_F 2496
#define WBUF_F 9216
#define X_CI   312
#define X_ROW  76
#define W_TAP  1024

__device__ __forceinline__ uint32_t s2u(const void* p) {
    uint32_t a;
    asm("{ .reg .u64 t; cvta.to.shared.u64 t, %1; cvt.u32.u64 %0, t; }" : "=r"(a) : "l"(p));
    return a;
}

#define CP16(dst_u32, src_ptr) \
    asm volatile("cp.async.cg.shared.global [%0], [%1], 16;" :: "r"(dst_u32), "l"(src_ptr))

#define MMA_TF32(c, a, b0v, b1v)                                                  \
    asm volatile("mma.sync.aligned.m16n8k8.row.col.f32.tf32.tf32.f32 "            \
                 "{%0,%1,%2,%3}, {%4,%5,%6,%7}, {%8,%9}, {%0,%1,%2,%3};"          \
                 : "+f"((c)[0]), "+f"((c)[1]), "+f"((c)[2]), "+f"((c)[3])         \
                 : "r"((a)[0]), "r"((a)[1]), "r"((a)[2]), "r"((a)[3]),            \
                   "r"(b0v), "r"(b1v))

__global__ __launch_bounds__(256, 2)
void resconv_mma(const float* __restrict__ inp, float* __restrict__ out)
{
    extern __shared__ float smf[];
    uint32_t* smu = (uint32_t*)smf;

    const int tid  = threadIdx.x;
    const int lane = tid & 31;
    const int wid  = tid >> 5;
    const int wm   = wid & 1;        // 0..1 : co half (64)
    const int wn   = wid >> 1;       // 0..3 : n group (32)
    const int lr   = lane >> 2;      // 0..7
    const int lc   = lane & 3;       // 0..3

    const int h0 = blockIdx.x * 2;
    const int b  = blockIdx.y;

    const uint32_t sbase = s2u(smf);
    const uint32_t* xsrc = g_xt + (size_t)b * Cc * Hh * Ww;
    const uint32_t* wsrc = g_wt + (size_t)b * 9 * Cc * Cc;

    // zero X buffers once (halo zeros are loop-invariant)
    for (int i = tid; i < 2 * XBUF_F; i += 256) smf[i] = 0.f;
    __syncthreads();

    float acc[4][4][4];
#pragma unroll
    for (int i = 0; i < 4; i++)
#pragma unroll
        for (int j = 0; j < 4; j++)
#pragma unroll
            for (int k = 0; k < 4; k++) acc[i][j][k] = 0.f;

    auto stageX = [&](int ci0, int xoff) {
#pragma unroll
        for (int it = 0; it < 2; it++) {
            int idx = tid + it * 256;       // 0..511
            int ci  = idx >> 6;
            int rem = idx & 63;
            int row = rem >> 4;
            int seg = rem & 15;
            int gh  = h0 + row - 1;
            if ((unsigned)gh < (unsigned)Hh) {
                const uint32_t* src = xsrc + ((size_t)(ci0 + ci) * Hh + gh) * Ww + seg * 4;
                uint32_t dst = sbase + 4u * (uint32_t)(xoff + ci * X_CI + row * X_ROW + 4 + seg * 4);
                CP16(dst, src);
            }
        }
    };
    auto stageW = [&](int ci0, int woff) {
#pragma unroll
        for (int it = 0; it < 9; it++) {
            int idx  = tid + it * 256;      // 0..2303
            int half = idx & 1;
            int co   = (idx >> 1) & 127;
            int tap  = idx >> 8;
            const uint32_t* src = wsrc + ((size_t)tap * Cc + co) * Cc + ci0 + half * 4;
            int dhalf = half ^ ((co >> 2) & 1);      // XOR-4 slot swizzle
            uint32_t dst = sbase + 4u * (uint32_t)(woff + tap * W_TAP + co * 8 + dhalf * 4);
            CP16(dst, src);
        }
        asm volatile("cp.async.commit_group;" ::: "memory");
    };

    stageX(0, 0);
    stageW(0, 2 * XBUF_F);
    asm volatile("cp.async.wait_group 0;" ::: "memory");
    __syncthreads();

    for (int kc = 0; kc < 16; kc++) {
        const int cur  = kc & 1;
        const int xoff = cur * XBUF_F;
        const int woff = 2 * XBUF_F + cur * WBUF_F;

        if (kc < 15) {
            stageX((kc + 1) * 8, (cur ^ 1) * XBUF_F);
            stageW((kc + 1) * 8, 2 * XBUF_F + (cur ^ 1) * WBUF_F);
        }

#pragma unroll
        for (int kh = 0; kh < 3; kh++) {
#pragma unroll
            for (int kw = 0; kw < 3; kw++) {
                const int t = kh * 3 + kw;
                const uint32_t* pw = smu + woff + t * W_TAP;
                uint32_t a[4][4];
#pragma unroll
                for (int tm = 0; tm < 4; tm++) {
                    const int cob = wm * 64 + tm * 16 + lr;
                    const int x4  = cob & 4;
                    const uint32_t* p = pw + cob * 8;
                    a[tm][0] = p[lc ^ x4];
                    a[tm][1] = p[64 + (lc ^ x4)];
                    a[tm][2] = p[(lc + 4) ^ x4];
                    a[tm][3] = p[64 + ((lc + 4) ^ x4)];
                }
#pragma unroll
                for (int tn = 0; tn < 4; tn++) {
                    const int n0 = wn * 32 + tn * 8;
                    const int r  = n0 >> 6;
                    const int x  = (n0 & 63) + lr;
                    const uint32_t* q = smu + xoff + lc * X_CI + (r + kh) * X_ROW + x + kw + 3;
                    uint32_t b0 = q[0];
                    uint32_t b1 = q[4 * X_CI];
#pragma unroll
                    for (int tm = 0; tm < 4; tm++)
                        MMA_TF32(acc[tm][tn], a[tm], b0, b1);
                }
            }
        }

        asm volatile("cp.async.wait_group 0;" ::: "memory");
        __syncthreads();
    }

    // epilogue: out = inp + conv
#pragma unroll
    for (int tm = 0; tm < 4; tm++) {
#pragma unroll
        for (int tn = 0; tn < 4; tn++) {
            const int n = wn * 32 + tn * 8 + lc * 2;
            const int h = h0 + (n >> 6);
            const int w = n & 63;
            const int co0 = wm * 64 + tm * 16 + lr;
#pragma unroll
            for (int half = 0; half < 2; half++) {
                const int co = co0 + half * 8;
                const size_t off = ((size_t)(b * Cc + co) * Hh + h) * Ww + w;
                float2 rv = *(const float2*)(inp + off);
                float2 ov;
                ov.x = rv.x + acc[tm][tn][half * 2 + 0];
                ov.y = rv.y + acc[tm][tn][half * 2 + 1];
                *(float2*)(out + off) = ov;
            }
        }
    }
}

extern "C" void kernel_launch(void* const* d_in, const int* in_sizes, int n_in,
                              void* d_out, int out_size)
{
    const float* inp = (const float*)d_in[0];   // [16,128,64,64]
    const float* wgt = (const float*)d_in[1];   // [16,128,128,3,3]
    float* out = (float*)d_out;

    prep_w<<<(Bn * 9 * Cc * Cc) / 512, 512>>>(wgt);
    prep_x<<<(Bn * Cc * Hh * Ww / 4) / 256, 256>>>(inp);

    const int smem_bytes = (2 * XBUF_F + 2 * WBUF_F) * 4;   // 93696
    cudaFuncSetAttribute(resconv_mma, cudaFuncAttributeMaxDynamicSharedMemorySize, smem_bytes);
    dim3 grid(Hh / 2, Bn);   // (32, 16) = 512 CTAs
    resconv_mma<<<grid, 256, smem_bytes>>>(inp, out);
}